// round 9
// baseline (speedup 1.0000x reference)
#include <cuda_runtime.h>
#include <cuda_fp16.h>
#include <math.h>

#define SZ_LOG 25
#define SZ (1u << SZ_LOG)          // 33554432
#define FD 30000000u               // FLAT_DIM
#define LOW_TILE 8192              // 2^13, low-pass tile

// fp16 range guard: FWHT2 intermediates reach std ~5e5, so pre-scale the
// second-transform data path by 2^-12 (exact in fp16) and undo at the end.
#define PRESCALE   (1.0f / 4096.0f)
#define UNPRESCALE 4096.0f

// Scratch (allocation-free rule): two fp16 ping-pong buffers, 64MB each.
__device__ __half g_h0[SZ];
__device__ __half g_h1[SZ];

// L2 eviction-priority via createpolicy + cache_hint (scalar-width legal form
// on sm_103a): keep the gather-source array (h0) resident against the 320MB
// of Pi/G/h1 streaming traffic.
__device__ __forceinline__ unsigned long long mk_keep_policy() {
    unsigned long long pol;
    asm volatile("createpolicy.fractional.L2::evict_last.b64 %0, 1.0;" : "=l"(pol));
    return pol;
}
__device__ __forceinline__ __half ldg_keep_h(const __half* p, unsigned long long pol) {
    unsigned short r;
    asm volatile("ld.global.nc.L2::cache_hint.b16 %0, [%1], %2;"
                 : "=h"(r) : "l"(p), "l"(pol));
    return __ushort_as_half(r);
}
__device__ __forceinline__ void stg_keep_h(__half* p, __half v, unsigned long long pol) {
    asm volatile("st.global.L2::cache_hint.b16 [%0], %1, %2;"
                 :: "l"(p), "h"(__half_as_ushort(v)), "l"(pol) : "memory");
}

// ---------------------------------------------------------------------------
// Fully-unrolled in-register FWHT over N floats
// ---------------------------------------------------------------------------
template <int N>
__device__ __forceinline__ void fwhtN(float* v) {
#pragma unroll
    for (int h = 1; h < N; h <<= 1) {
#pragma unroll
        for (int s = 0; s < N; s += 2 * h) {
#pragma unroll
            for (int k = 0; k < h; k++) {
                float a = v[s + k];
                float b = v[s + k + h];
                v[s + k]     = a + b;
                v[s + k + h] = a - b;
            }
        }
    }
}

// Shared swizzle: conflict-free for all three low-pass access patterns.
__device__ __forceinline__ int sw(int a) { return a ^ ((a >> 5) & 31); }

// ---------------------------------------------------------------------------
// Low pass: butterflies on bits 0..12 over contiguous 8192-element tiles.
// 256 threads x 32 elements/thread.
// MODE 0 (stream-bound): x = pad(theta)*B; (256,3) launch bounds.
// MODE 1 (gather, L1-wavefront-bound): x = srcH[Pi[i]]*G[i]*PRESCALE;
//   (256,4) -> 64-reg target -> 32 warps/SM for max outstanding gathers.
// Phases: fwht32 on bits 8..12 | fwht32 on bits 3..7 | fwht8 on bits 0..2.
// ---------------------------------------------------------------------------
template <int MODE>
__global__ __launch_bounds__(256, (MODE == 1 ? 4 : 3)) void k_low(
    const float*  __restrict__ theta, const float* __restrict__ Bv,
    const __half* __restrict__ srcH,  const int*   __restrict__ Pi,
    const float*  __restrict__ G,     __half*      __restrict__ dst)
{
    __shared__ float s[LOW_TILE];
    const int t = threadIdx.x;                       // 0..255
    const unsigned base = blockIdx.x * LOW_TILE;

    float v[32];
    if (MODE == 0) {
#pragma unroll
        for (int j = 0; j < 32; j++) {
            unsigned idx = base + (unsigned)j * 256u + (unsigned)t;
            float th = (idx < FD) ? __ldcs(&theta[idx]) : 0.0f;
            v[j] = th * __ldcs(&Bv[idx]);
        }
    } else {
        const unsigned long long pol = mk_keep_policy();
        // Rolling 8-deep prefetch of Pi and G keeps regs ~64 while the
        // gather latency is covered by warp count (32 warps/SM).
#pragma unroll
        for (int jb = 0; jb < 32; jb += 8) {
            int   pidx[8];
            float g[8];
#pragma unroll
            for (int k = 0; k < 8; k++) {
                unsigned idx = base + (unsigned)(jb + k) * 256u + (unsigned)t;
                pidx[k] = __ldcs(&Pi[idx]);
                g[k]    = __ldcs(&G[idx]) * PRESCALE;
            }
#pragma unroll
            for (int k = 0; k < 8; k++)
                // Random 2B gather over the 64MB L2-resident array:
                // evict_last policy pins hot lines against stream pollution.
                v[jb + k] = __half2float(ldg_keep_h(&srcH[pidx[k]], pol)) * g[k];
        }
    }

    fwhtN<32>(v);  // bits 8..12  (e = j*256 + t)

#pragma unroll
    for (int j = 0; j < 32; j++) s[sw(j * 256 + t)] = v[j];
    __syncthreads();

    // Phase B: thread owns bits 3..7; fixed bits 0..2 = t&7, bits 8..12 = t>>3.
    {
        const int m = t >> 3, r = t & 7;
#pragma unroll
        for (int k = 0; k < 32; k++) v[k] = s[sw(m * 256 + k * 8 + r)];

        fwhtN<32>(v);  // bits 3..7

#pragma unroll
        for (int k = 0; k < 32; k++) s[sw(m * 256 + k * 8 + r)] = v[k];
    }
    __syncthreads();

    // Phase C: 4 octets per thread; fwht8 on bits 0..2, 16B coalesced stores.
#pragma unroll
    for (int g = 0; g < 4; g++) {
        float w[8];
        const int ebase = g * 2048 + t * 8;
#pragma unroll
        for (int b = 0; b < 8; b++) w[b] = s[sw(ebase + b)];

        fwhtN<8>(w);   // bits 0..2

        __half h[8];
#pragma unroll
        for (int b = 0; b < 8; b++) h[b] = __float2half_rn(w[b]);

        uint4 pack = *reinterpret_cast<uint4*>(h);
        uint4* p = reinterpret_cast<uint4*>(&dst[base + (unsigned)ebase]);
        if (MODE == 1) __stcs(p, pack);   // h1 is a stream; protect gather-src L2
        else           *p = pack;         // h0 will be gathered: keep in L2
    }
}

// ---------------------------------------------------------------------------
// 6-bit streaming butterfly pass at element stride S.
// Each thread privately owns 64 elements {base + j*S}; warp loads are 64B
// contiguous runs. No shared memory, no barriers, pure MLP stream.
//   S = 8192   -> global bits 13..18
//   S = 524288 -> global bits 19..24
// KEEP=1 (FWHT1 final pass): store with evict_last policy — this array is the
//   gather source for the next kernel.
// FINAL=1: fp32 output truncated to FD, scaled by
//          UNPRESCALE / (divisor*sqrt(FD/SZ)).
// ---------------------------------------------------------------------------
template <unsigned S, int FINAL, int KEEP>
__global__ __launch_bounds__(256) void k_h6(
    __half* __restrict__ buf, float* __restrict__ out,
    const float* __restrict__ divisor)
{
    const unsigned t     = threadIdx.x;
    const unsigned cpg   = S / 256u;                 // chunks per 64*S group
    const unsigned group = blockIdx.x / cpg;
    const unsigned chunk = blockIdx.x % cpg;
    const unsigned base  = group * (S * 64u) + chunk * 256u + t;

    float v[64];
#pragma unroll
    for (int j = 0; j < 64; j++)
        v[j] = __half2float(__ldcg(&buf[base + (unsigned)j * S]));

    fwhtN<64>(v);

    if (FINAL) {
        const float scale = UNPRESCALE / (divisor[0] * sqrtf((float)FD / (float)SZ));
#pragma unroll
        for (int j = 0; j < 64; j++) {
            unsigned idx = base + (unsigned)j * S;
            if (idx < FD) __stcs(&out[idx], v[j] * scale);
        }
    } else if (KEEP) {
        const unsigned long long pol = mk_keep_policy();
#pragma unroll
        for (int j = 0; j < 64; j++)
            stg_keep_h(&buf[base + (unsigned)j * S], __float2half_rn(v[j]), pol);
    } else {
#pragma unroll
        for (int j = 0; j < 64; j++)
            buf[base + (unsigned)j * S] = __float2half_rn(v[j]);
    }
}

// ---------------------------------------------------------------------------
// kernel_launch: 6 graph-capturable launches, no allocs, no syncs.
// ---------------------------------------------------------------------------
extern "C" void kernel_launch(void* const* d_in, const int* in_sizes, int n_in,
                              void* d_out, int out_size)
{
    const float* theta   = (const float*)d_in[0];
    const float* G       = (const float*)d_in[1];
    const float* B       = (const float*)d_in[2];
    const float* divisor = (const float*)d_in[3];
    const int*   Pi      = (const int*)d_in[4];
    float*       out     = (float*)d_out;

    __half *h0, *h1;
    cudaGetSymbolAddress((void**)&h0, g_h0);
    cudaGetSymbolAddress((void**)&h1, g_h1);

    const int low_grid = SZ / LOW_TILE;        // 4096
    const int h6_grid  = SZ / (64 * 256);      // 2048

    // FWHT #1: pad*B + bits 0..12 -> h0; bits 13..18; bits 19..24 (in place,
    // final pass stores evict_last: h0 is the upcoming gather source).
    k_low<0><<<low_grid, 256>>>(theta, B, nullptr, nullptr, nullptr, h0);
    k_h6<8192u,   0, 0><<<h6_grid, 256>>>(h0, nullptr, nullptr);
    k_h6<524288u, 0, 1><<<h6_grid, 256>>>(h0, nullptr, nullptr);

    // FWHT #2: gather(Pi)*G (pre-scaled) + bits 0..12 -> h1;
    //          bits 13..18; bits 19..24 + final scale.
    k_low<1><<<low_grid, 256>>>(nullptr, nullptr, h0, Pi, G, h1);
    k_h6<8192u,   0, 0><<<h6_grid, 256>>>(h1, nullptr, nullptr);
    k_h6<524288u, 1, 0><<<h6_grid, 256>>>(h1, out, divisor);
}

// round 10
// speedup vs baseline: 1.0447x; 1.0447x over previous
#include <cuda_runtime.h>
#include <cuda_fp16.h>
#include <math.h>

#define SZ_LOG 25
#define SZ (1u << SZ_LOG)          // 33554432
#define FD 30000000u               // FLAT_DIM
#define LOW_TILE 8192              // 2^13, low-pass tile

// fp16 range guard: FWHT2 intermediates reach std ~5e5, so pre-scale the
// second-transform data path by 2^-12 (exact in fp16) and undo at the end.
#define PRESCALE   (1.0f / 4096.0f)
#define UNPRESCALE 4096.0f

// Scratch (allocation-free rule): two fp16 ping-pong buffers, 64MB each.
__device__ __half g_h0[SZ];
__device__ __half g_h1[SZ];

// ---------------------------------------------------------------------------
// Fully-unrolled in-register FWHT over N floats
// ---------------------------------------------------------------------------
template <int N>
__device__ __forceinline__ void fwhtN(float* v) {
#pragma unroll
    for (int h = 1; h < N; h <<= 1) {
#pragma unroll
        for (int s = 0; s < N; s += 2 * h) {
#pragma unroll
            for (int k = 0; k < h; k++) {
                float a = v[s + k];
                float b = v[s + k + h];
                v[s + k]     = a + b;
                v[s + k + h] = a - b;
            }
        }
    }
}

// Shared swizzle: conflict-free for all three low-pass access patterns.
__device__ __forceinline__ int sw(int a) { return a ^ ((a >> 5) & 31); }

// ---------------------------------------------------------------------------
// Low pass: butterflies on bits 0..12 over contiguous 8192-element tiles.
// 256 threads x 32 elements/thread.
// MODE 0 (stream-bound): x = pad(theta)*B; (256,3) launch bounds; B loaded
//   unconditionally (R7's conditional-skip variant measured slower).
// MODE 1 (gather, l1tex-wavefront-bound at its throughput ceiling):
//   x = srcH[Pi[i]]*G[i]*PRESCALE; (256,4) -> 64 regs -> 32 warps/SM.
// Phases: fwht32 on bits 8..12 | fwht32 on bits 3..7 | fwht8 on bits 0..2.
// ---------------------------------------------------------------------------
template <int MODE>
__global__ __launch_bounds__(256, (MODE == 1 ? 4 : 3)) void k_low(
    const float*  __restrict__ theta, const float* __restrict__ Bv,
    const __half* __restrict__ srcH,  const int*   __restrict__ Pi,
    const float*  __restrict__ G,     __half*      __restrict__ dst)
{
    __shared__ float s[LOW_TILE];
    const int t = threadIdx.x;                       // 0..255
    const unsigned base = blockIdx.x * LOW_TILE;

    float v[32];
    if (MODE == 0) {
#pragma unroll
        for (int j = 0; j < 32; j++) {
            unsigned idx = base + (unsigned)j * 256u + (unsigned)t;
            float th = (idx < FD) ? __ldcs(&theta[idx]) : 0.0f;
            v[j] = th * __ldcs(&Bv[idx]);
        }
    } else {
        // Rolling 8-deep prefetch of Pi and G keeps regs ~64 while gather
        // latency is covered by warp count (32 warps/SM).
#pragma unroll
        for (int jb = 0; jb < 32; jb += 8) {
            int   pidx[8];
            float g[8];
#pragma unroll
            for (int k = 0; k < 8; k++) {
                unsigned idx = base + (unsigned)(jb + k) * 256u + (unsigned)t;
                pidx[k] = __ldcs(&Pi[idx]);
                g[k]    = __ldcs(&G[idx]) * PRESCALE;
            }
#pragma unroll
            for (int k = 0; k < 8; k++)
                // Random 2B gather over the 64MB L2-resident array: L2-only,
                // default eviction (policy experiments measured slower).
                v[jb + k] = __half2float(__ldcg(&srcH[pidx[k]])) * g[k];
        }
    }

    fwhtN<32>(v);  // bits 8..12  (e = j*256 + t)

#pragma unroll
    for (int j = 0; j < 32; j++) s[sw(j * 256 + t)] = v[j];
    __syncthreads();

    // Phase B: thread owns bits 3..7; fixed bits 0..2 = t&7, bits 8..12 = t>>3.
    {
        const int m = t >> 3, r = t & 7;
#pragma unroll
        for (int k = 0; k < 32; k++) v[k] = s[sw(m * 256 + k * 8 + r)];

        fwhtN<32>(v);  // bits 3..7

#pragma unroll
        for (int k = 0; k < 32; k++) s[sw(m * 256 + k * 8 + r)] = v[k];
    }
    __syncthreads();

    // Phase C: 4 octets per thread; fwht8 on bits 0..2, 16B coalesced stores.
#pragma unroll
    for (int g = 0; g < 4; g++) {
        float w[8];
        const int ebase = g * 2048 + t * 8;
#pragma unroll
        for (int b = 0; b < 8; b++) w[b] = s[sw(ebase + b)];

        fwhtN<8>(w);   // bits 0..2

        __half h[8];
#pragma unroll
        for (int b = 0; b < 8; b++) h[b] = __float2half_rn(w[b]);

        uint4 pack = *reinterpret_cast<uint4*>(h);
        uint4* p = reinterpret_cast<uint4*>(&dst[base + (unsigned)ebase]);
        if (MODE == 1) __stcs(p, pack);   // h1 is a stream; protect gather-src L2
        else           *p = pack;         // h0 will be gathered: keep in L2
    }
}

// ---------------------------------------------------------------------------
// 6-bit streaming butterfly pass at element stride S.
// Each thread privately owns 64 elements {base + j*S}; warp loads are 64B
// contiguous runs. No shared memory, no barriers, pure MLP stream.
//   S = 8192   -> global bits 13..18
//   S = 524288 -> global bits 19..24
// FINAL=1: fp32 output truncated to FD, scaled by
//          UNPRESCALE / (divisor*sqrt(FD/SZ)).
// ---------------------------------------------------------------------------
template <unsigned S, int FINAL>
__global__ __launch_bounds__(256) void k_h6(
    __half* __restrict__ buf, float* __restrict__ out,
    const float* __restrict__ divisor)
{
    const unsigned t     = threadIdx.x;
    const unsigned cpg   = S / 256u;                 // chunks per 64*S group
    const unsigned group = blockIdx.x / cpg;
    const unsigned chunk = blockIdx.x % cpg;
    const unsigned base  = group * (S * 64u) + chunk * 256u + t;

    float v[64];
#pragma unroll
    for (int j = 0; j < 64; j++)
        v[j] = __half2float(__ldcg(&buf[base + (unsigned)j * S]));

    fwhtN<64>(v);

    if (FINAL) {
        const float scale = UNPRESCALE / (divisor[0] * sqrtf((float)FD / (float)SZ));
#pragma unroll
        for (int j = 0; j < 64; j++) {
            unsigned idx = base + (unsigned)j * S;
            if (idx < FD) __stcs(&out[idx], v[j] * scale);
        }
    } else {
#pragma unroll
        for (int j = 0; j < 64; j++)
            buf[base + (unsigned)j * S] = __float2half_rn(v[j]);
    }
}

// ---------------------------------------------------------------------------
// kernel_launch: 6 graph-capturable launches, no allocs, no syncs.
// ---------------------------------------------------------------------------
extern "C" void kernel_launch(void* const* d_in, const int* in_sizes, int n_in,
                              void* d_out, int out_size)
{
    const float* theta   = (const float*)d_in[0];
    const float* G       = (const float*)d_in[1];
    const float* B       = (const float*)d_in[2];
    const float* divisor = (const float*)d_in[3];
    const int*   Pi      = (const int*)d_in[4];
    float*       out     = (float*)d_out;

    __half *h0, *h1;
    cudaGetSymbolAddress((void**)&h0, g_h0);
    cudaGetSymbolAddress((void**)&h1, g_h1);

    const int low_grid = SZ / LOW_TILE;        // 4096
    const int h6_grid  = SZ / (64 * 256);      // 2048

    // FWHT #1: pad*B + bits 0..12 -> h0; bits 13..18; bits 19..24 (in place).
    k_low<0><<<low_grid, 256>>>(theta, B, nullptr, nullptr, nullptr, h0);
    k_h6<8192u,   0><<<h6_grid, 256>>>(h0, nullptr, nullptr);
    k_h6<524288u, 0><<<h6_grid, 256>>>(h0, nullptr, nullptr);

    // FWHT #2: gather(Pi)*G (pre-scaled) + bits 0..12 -> h1;
    //          bits 13..18; bits 19..24 + final scale.
    k_low<1><<<low_grid, 256>>>(nullptr, nullptr, h0, Pi, G, h1);
    k_h6<8192u,   0><<<h6_grid, 256>>>(h1, nullptr, nullptr);
    k_h6<524288u, 1><<<h6_grid, 256>>>(h1, out, divisor);
}

// round 11
// speedup vs baseline: 1.0631x; 1.0176x over previous
#include <cuda_runtime.h>
#include <cuda_fp16.h>
#include <math.h>

#define SZ_LOG 25
#define SZ (1u << SZ_LOG)          // 33554432
#define FD 30000000u               // FLAT_DIM
#define LOW_TILE 8192              // 2^13, low-pass tile

// fp16 range guard: FWHT2 intermediates reach std ~5e5, so pre-scale the
// second-transform data path by 2^-12 (exact in fp16) and undo at the end.
#define PRESCALE   (1.0f / 4096.0f)
#define UNPRESCALE 4096.0f

// Scratch (allocation-free rule): two fp16 ping-pong buffers, 64MB each.
__device__ __half g_h0[SZ];
__device__ __half g_h1[SZ];

// Raw 2B gather, L2-only (random lines would waste L1), result as uint.
__device__ __forceinline__ unsigned ldg_u16_cg(const __half* p) {
    unsigned short r;
    asm volatile("ld.global.cg.u16 %0, [%1];" : "=h"(r) : "l"(p));
    return (unsigned)r;
}

// ---------------------------------------------------------------------------
// Fully-unrolled in-register FWHT over N floats
// ---------------------------------------------------------------------------
template <int N>
__device__ __forceinline__ void fwhtN(float* v) {
#pragma unroll
    for (int h = 1; h < N; h <<= 1) {
#pragma unroll
        for (int s = 0; s < N; s += 2 * h) {
#pragma unroll
            for (int k = 0; k < h; k++) {
                float a = v[s + k];
                float b = v[s + k + h];
                v[s + k]     = a + b;
                v[s + k + h] = a - b;
            }
        }
    }
}

// Shared swizzle: conflict-free for all three low-pass access patterns.
__device__ __forceinline__ int sw(int a) { return a ^ ((a >> 5) & 31); }

// ---------------------------------------------------------------------------
// Low pass: butterflies on bits 0..12 over contiguous 8192-element tiles.
// 256 threads x 32 elements/thread.
// MODE 0 (stream-bound): x = pad(theta)*B.
// MODE 1 (gather, l1tex-wavefront-bound): x = srcH[Pi[i]]*G[i]*PRESCALE.
//   32-deep gather pipeline via register aliasing: Pi indices staged in v[]
//   (bit-cast), each overwritten by its own gather result -> 32 outstanding
//   gathers per warp x 32 warps/SM = wf-pipe saturation.
// Phases: fwht32 on bits 8..12 | fwht32 on bits 3..7 | fwht8 on bits 0..2.
// ---------------------------------------------------------------------------
template <int MODE>
__global__ __launch_bounds__(256, (MODE == 1 ? 4 : 3)) void k_low(
    const float*  __restrict__ theta, const float* __restrict__ Bv,
    const __half* __restrict__ srcH,  const int*   __restrict__ Pi,
    const float*  __restrict__ G,     __half*      __restrict__ dst)
{
    __shared__ float s[LOW_TILE];
    const int t = threadIdx.x;                       // 0..255
    const unsigned base = blockIdx.x * LOW_TILE;

    float v[32];
    if (MODE == 0) {
#pragma unroll
        for (int j = 0; j < 32; j++) {
            unsigned idx = base + (unsigned)j * 256u + (unsigned)t;
            float th = (idx < FD) ? __ldcs(&theta[idx]) : 0.0f;
            v[j] = th * __ldcs(&Bv[idx]);
        }
    } else {
        // Stage 1: 32 coalesced Pi loads, results parked in v[] as ints.
#pragma unroll
        for (int j = 0; j < 32; j++)
            v[j] = __int_as_float(__ldcs(&Pi[base + (unsigned)j * 256u + (unsigned)t]));
        // Stage 2: 32 independent random gathers, each overwriting its own
        // address register (max in-flight per warp).
#pragma unroll
        for (int j = 0; j < 32; j++)
            v[j] = __uint_as_float(ldg_u16_cg(&srcH[__float_as_int(v[j])]));
        // Stage 3: convert + multiply by G (fresh coalesced stream loads).
#pragma unroll
        for (int j = 0; j < 32; j++) {
            unsigned idx = base + (unsigned)j * 256u + (unsigned)t;
            float x = __half2float(__ushort_as_half(
                          (unsigned short)__float_as_uint(v[j])));
            v[j] = x * (__ldcs(&G[idx]) * PRESCALE);
        }
    }

    fwhtN<32>(v);  // bits 8..12  (e = j*256 + t)

#pragma unroll
    for (int j = 0; j < 32; j++) s[sw(j * 256 + t)] = v[j];
    __syncthreads();

    // Phase B: thread owns bits 3..7; fixed bits 0..2 = t&7, bits 8..12 = t>>3.
    {
        const int m = t >> 3, r = t & 7;
#pragma unroll
        for (int k = 0; k < 32; k++) v[k] = s[sw(m * 256 + k * 8 + r)];

        fwhtN<32>(v);  // bits 3..7

#pragma unroll
        for (int k = 0; k < 32; k++) s[sw(m * 256 + k * 8 + r)] = v[k];
    }
    __syncthreads();

    // Phase C: 4 octets per thread; fwht8 on bits 0..2, 16B coalesced stores.
#pragma unroll
    for (int g = 0; g < 4; g++) {
        float w[8];
        const int ebase = g * 2048 + t * 8;
#pragma unroll
        for (int b = 0; b < 8; b++) w[b] = s[sw(ebase + b)];

        fwhtN<8>(w);   // bits 0..2

        __half h[8];
#pragma unroll
        for (int b = 0; b < 8; b++) h[b] = __float2half_rn(w[b]);

        uint4 pack = *reinterpret_cast<uint4*>(h);
        uint4* p = reinterpret_cast<uint4*>(&dst[base + (unsigned)ebase]);
        if (MODE == 1) __stcs(p, pack);   // h1 is a stream; protect gather-src L2
        else           *p = pack;         // h0 will be gathered: keep in L2
    }
}

// ---------------------------------------------------------------------------
// 6-bit streaming butterfly pass at element stride S.
// Each thread privately owns 64 elements {base + j*S}; warp loads are 64B
// contiguous runs. No shared memory, no barriers, pure MLP stream.
//   S = 8192   -> global bits 13..18
//   S = 524288 -> global bits 19..24
// FINAL=1: fp32 output truncated to FD, scaled by
//          UNPRESCALE / (divisor*sqrt(FD/SZ)).
// ---------------------------------------------------------------------------
template <unsigned S, int FINAL>
__global__ __launch_bounds__(256) void k_h6(
    __half* __restrict__ buf, float* __restrict__ out,
    const float* __restrict__ divisor)
{
    const unsigned t     = threadIdx.x;
    const unsigned cpg   = S / 256u;                 // chunks per 64*S group
    const unsigned group = blockIdx.x / cpg;
    const unsigned chunk = blockIdx.x % cpg;
    const unsigned base  = group * (S * 64u) + chunk * 256u + t;

    float v[64];
#pragma unroll
    for (int j = 0; j < 64; j++)
        v[j] = __half2float(__ldcg(&buf[base + (unsigned)j * S]));

    fwhtN<64>(v);

    if (FINAL) {
        const float scale = UNPRESCALE / (divisor[0] * sqrtf((float)FD / (float)SZ));
#pragma unroll
        for (int j = 0; j < 64; j++) {
            unsigned idx = base + (unsigned)j * S;
            if (idx < FD) __stcs(&out[idx], v[j] * scale);
        }
    } else {
#pragma unroll
        for (int j = 0; j < 64; j++)
            buf[base + (unsigned)j * S] = __float2half_rn(v[j]);
    }
}

// ---------------------------------------------------------------------------
// kernel_launch: 6 graph-capturable launches, no allocs, no syncs.
// ---------------------------------------------------------------------------
extern "C" void kernel_launch(void* const* d_in, const int* in_sizes, int n_in,
                              void* d_out, int out_size)
{
    const float* theta   = (const float*)d_in[0];
    const float* G       = (const float*)d_in[1];
    const float* B       = (const float*)d_in[2];
    const float* divisor = (const float*)d_in[3];
    const int*   Pi      = (const int*)d_in[4];
    float*       out     = (float*)d_out;

    __half *h0, *h1;
    cudaGetSymbolAddress((void**)&h0, g_h0);
    cudaGetSymbolAddress((void**)&h1, g_h1);

    const int low_grid = SZ / LOW_TILE;        // 4096
    const int h6_grid  = SZ / (64 * 256);      // 2048

    // FWHT #1: pad*B + bits 0..12 -> h0; bits 13..18; bits 19..24 (in place).
    k_low<0><<<low_grid, 256>>>(theta, B, nullptr, nullptr, nullptr, h0);
    k_h6<8192u,   0><<<h6_grid, 256>>>(h0, nullptr, nullptr);
    k_h6<524288u, 0><<<h6_grid, 256>>>(h0, nullptr, nullptr);

    // FWHT #2: gather(Pi)*G (pre-scaled) + bits 0..12 -> h1;
    //          bits 13..18; bits 19..24 + final scale.
    k_low<1><<<low_grid, 256>>>(nullptr, nullptr, h0, Pi, G, h1);
    k_h6<8192u,   0><<<h6_grid, 256>>>(h1, nullptr, nullptr);
    k_h6<524288u, 1><<<h6_grid, 256>>>(h1, out, divisor);
}